// round 1
// baseline (speedup 1.0000x reference)
#include <cuda_runtime.h>
#include <cstdint>

#define N_NODES_MAX 100000
#define HID   52
#define HID2  104
#define NL    3
#define VPR   13   // float4 per 52-float row (52*4 = 208 bytes, 16B aligned)

// Scratch (allocation-free): layer outputs h1,h2,h3 and the z buffer.
__device__ float g_h[NL][N_NODES_MAX * HID];
__device__ float g_z[N_NODES_MAX * HID];

// ---------------------------------------------------------------------------
// z = (1 + eps[l]) * h_in      (vectorized over float4)
// ---------------------------------------------------------------------------
__global__ void init_z_kernel(const float* __restrict__ x,
                              const float* __restrict__ eps,
                              int l, int n)
{
    int i = blockIdx.x * blockDim.x + threadIdx.x;
    int total4 = n * VPR;
    if (i >= total4) return;
    const float* hin = (l == 0) ? x : g_h[l - 1];
    float s = 1.0f + eps[l];
    float4 v = ((const float4*)hin)[i];
    v.x *= s; v.y *= s; v.z *= s; v.w *= s;
    ((float4*)g_z)[i] = v;
}

// ---------------------------------------------------------------------------
// z[dst] += h_in[src]   — one thread per (edge, float4-chunk).
// 13 consecutive threads share one edge; gather of the 208B source row is
// contiguous, reduction uses red.global.add.v4.f32 (no return trip).
// ---------------------------------------------------------------------------
__global__ void scatter_kernel(const float* __restrict__ x,
                               const int* __restrict__ ei,
                               int l, int E)
{
    int i = blockIdx.x * blockDim.x + threadIdx.x;
    if (i >= E * VPR) return;
    int e = i / VPR;
    int c = i - e * VPR;
    const float* hin = (l == 0) ? x : g_h[l - 1];
    int src = __ldg(&ei[e]);
    int dst = __ldg(&ei[E + e]);
    float4 v = ((const float4*)hin)[src * VPR + c];
    float* p = g_z + (size_t)dst * HID + c * 4;
    asm volatile("red.global.add.v4.f32 [%0], {%1, %2, %3, %4};"
                 :: "l"(p), "f"(v.x), "f"(v.y), "f"(v.z), "f"(v.w)
                 : "memory");
}

// ---------------------------------------------------------------------------
// Per-node 2-layer MLP: h_out = relu( relu(z @ w1 + b1) @ w2 + b2 )
// Thread-per-node. z (52) and acc (52) live in registers; weights broadcast
// from shared memory. j-loop rolled (code ~3.5KB, fits L0 I$), k/i unrolled.
// ---------------------------------------------------------------------------
__global__ void mlp_kernel(const float* __restrict__ w1,
                           const float* __restrict__ b1,
                           const float* __restrict__ w2,
                           const float* __restrict__ b2,
                           int l, int n)
{
    __shared__ float sw1[HID * HID2];   // [k][j]
    __shared__ float sw2[HID2 * HID];   // [j][i]
    __shared__ float sb1[HID2];
    __shared__ float sb2[HID];

    const float* w1l = w1 + (size_t)l * HID * HID2;
    const float* w2l = w2 + (size_t)l * HID2 * HID;
    for (int i = threadIdx.x; i < HID * HID2; i += blockDim.x) sw1[i] = w1l[i];
    for (int i = threadIdx.x; i < HID2 * HID; i += blockDim.x) sw2[i] = w2l[i];
    if (threadIdx.x < HID2) sb1[threadIdx.x] = b1[l * HID2 + threadIdx.x];
    if (threadIdx.x < HID)  sb2[threadIdx.x] = b2[l * HID + threadIdx.x];
    __syncthreads();

    int node = blockIdx.x * blockDim.x + threadIdx.x;
    if (node >= n) return;

    float zr[HID];
    const float4* zp = (const float4*)(g_z + (size_t)node * HID);
#pragma unroll
    for (int c = 0; c < VPR; c++) {
        float4 v = zp[c];
        zr[4*c+0] = v.x; zr[4*c+1] = v.y; zr[4*c+2] = v.z; zr[4*c+3] = v.w;
    }

    float acc[HID];
#pragma unroll
    for (int i = 0; i < HID; i++) acc[i] = 0.0f;

    for (int j = 0; j < HID2; j++) {
        float t = sb1[j];
#pragma unroll
        for (int k = 0; k < HID; k++) t = fmaf(zr[k], sw1[k * HID2 + j], t);
        t = fmaxf(t, 0.0f);
#pragma unroll
        for (int i = 0; i < HID; i++) acc[i] = fmaf(t, sw2[j * HID + i], acc[i]);
    }

    float4* op = (float4*)(g_h[l] + (size_t)node * HID);
#pragma unroll
    for (int c = 0; c < VPR; c++) {
        float4 v;
        v.x = fmaxf(acc[4*c+0] + sb2[4*c+0], 0.0f);
        v.y = fmaxf(acc[4*c+1] + sb2[4*c+1], 0.0f);
        v.z = fmaxf(acc[4*c+2] + sb2[4*c+2], 0.0f);
        v.w = fmaxf(acc[4*c+3] + sb2[4*c+3], 0.0f);
        op[c] = v;
    }
}

// ---------------------------------------------------------------------------
// Final: out = concat(x, h1, h2, h3) @ lin_w + lin_b
// ---------------------------------------------------------------------------
__global__ void final_kernel(const float* __restrict__ x,
                             const float* __restrict__ lw,
                             const float* __restrict__ lb,
                             float* __restrict__ out, int n)
{
    __shared__ float slw[(NL + 1) * HID * HID];  // 208 x 52 = 10816 floats
    __shared__ float slb[HID];
    for (int i = threadIdx.x; i < (NL + 1) * HID * HID; i += blockDim.x)
        slw[i] = lw[i];
    if (threadIdx.x < HID) slb[threadIdx.x] = lb[threadIdx.x];
    __syncthreads();

    int node = blockIdx.x * blockDim.x + threadIdx.x;
    if (node >= n) return;

    float acc[HID];
#pragma unroll
    for (int i = 0; i < HID; i++) acc[i] = slb[i];

#pragma unroll
    for (int s = 0; s < NL + 1; s++) {
        const float* hp = (s == 0) ? (x + (size_t)node * HID)
                                   : (g_h[s - 1] + (size_t)node * HID);
        const float* wp = slw + s * HID * HID;
        for (int k = 0; k < HID; k++) {
            float v = __ldg(&hp[k]);
#pragma unroll
            for (int i = 0; i < HID; i++) acc[i] = fmaf(v, wp[k * HID + i], acc[i]);
        }
    }

    float4* op = (float4*)(out + (size_t)node * HID);
#pragma unroll
    for (int c = 0; c < VPR; c++) {
        float4 v;
        v.x = acc[4*c+0]; v.y = acc[4*c+1]; v.z = acc[4*c+2]; v.w = acc[4*c+3];
        op[c] = v;
    }
}

// ---------------------------------------------------------------------------
extern "C" void kernel_launch(void* const* d_in, const int* in_sizes, int n_in,
                              void* d_out, int out_size)
{
    const float* x    = (const float*)d_in[0];   // [N, 52]
    const int*   ei   = (const int*)  d_in[1];   // [2, E]
    const float* w1   = (const float*)d_in[2];   // [3, 52, 104]
    const float* b1   = (const float*)d_in[3];   // [3, 104]
    const float* w2   = (const float*)d_in[4];   // [3, 104, 52]
    const float* b2   = (const float*)d_in[5];   // [3, 52]
    const float* eps  = (const float*)d_in[6];   // [3]
    const float* lw   = (const float*)d_in[7];   // [208, 52]
    const float* lb   = (const float*)d_in[8];   // [52]
    float* out = (float*)d_out;

    int n = in_sizes[0] / HID;
    int E = in_sizes[1] / 2;

    int initBlocks    = (n * VPR + 255) / 256;
    int scatterBlocks = (E * VPR + 255) / 256;
    int mlpBlocks     = (n + 127) / 128;

    for (int l = 0; l < NL; l++) {
        init_z_kernel<<<initBlocks, 256>>>(x, eps, l, n);
        scatter_kernel<<<scatterBlocks, 256>>>(x, ei, l, E);
        mlp_kernel<<<mlpBlocks, 128>>>(w1, b1, w2, b2, l, n);
    }
    final_kernel<<<mlpBlocks, 128>>>(x, lw, lb, out, n);
}

// round 2
// speedup vs baseline: 1.1137x; 1.1137x over previous
#include <cuda_runtime.h>
#include <cstdint>

#define N_NODES_MAX 100000
#define E_MAX       3200000
#define HID   52
#define HID2  104
#define NL    3
#define VPR   13   // float4 per 52-float row

// Scratch (allocation-free)
__device__ float g_h[NL][N_NODES_MAX * HID];
__device__ float g_z[N_NODES_MAX * HID];
__device__ int   g_deg[N_NODES_MAX];
__device__ int   g_rowptr[N_NODES_MAX];
__device__ int   g_cur[N_NODES_MAX];
__device__ int   g_csrc[E_MAX];

// ---------------------------------------------------------------------------
// CSR build: zero -> count -> scan -> place
// ---------------------------------------------------------------------------
__global__ void zero_deg_kernel(int n)
{
    int i = blockIdx.x * blockDim.x + threadIdx.x;
    if (i < n) g_deg[i] = 0;
}

__global__ void count_kernel(const int* __restrict__ ei, int E)
{
    int e = blockIdx.x * blockDim.x + threadIdx.x;
    if (e < E) atomicAdd(&g_deg[__ldg(&ei[E + e])], 1);  // no return use -> RED
}

// single-block chunked exclusive scan (Hillis-Steele, double buffered)
__global__ void scan_kernel(int n)
{
    __shared__ int s[2][1024];
    __shared__ int carry_s;
    int tid = threadIdx.x;
    if (tid == 0) carry_s = 0;
    __syncthreads();
    for (int base = 0; base < n; base += 1024) {
        int i = base + tid;
        int v = (i < n) ? g_deg[i] : 0;
        int cur = 0;
        s[0][tid] = v;
        __syncthreads();
        for (int off = 1; off < 1024; off <<= 1) {
            int nv = s[cur][tid] + ((tid >= off) ? s[cur][tid - off] : 0);
            s[1 - cur][tid] = nv;
            cur = 1 - cur;
            __syncthreads();
        }
        int incl = s[cur][tid];
        int base_carry = carry_s;
        int excl = base_carry + incl - v;
        if (i < n) { g_rowptr[i] = excl; g_cur[i] = excl; }
        __syncthreads();  // all threads read carry_s before update
        if (tid == 1023) carry_s = base_carry + s[cur][1023];
        __syncthreads();
    }
}

__global__ void place_kernel(const int* __restrict__ ei, int E)
{
    int e = blockIdx.x * blockDim.x + threadIdx.x;
    if (e >= E) return;
    int src = __ldg(&ei[e]);
    int dst = __ldg(&ei[E + e]);
    int pos = atomicAdd(&g_cur[dst], 1);
    g_csrc[pos] = src;
}

// ---------------------------------------------------------------------------
// Segmented sum (warp-per-node, lanes 0..12 each own one float4 chunk):
// z[node] = (1+eps)*h_in[node] + sum_{e in CSR[node]} h_in[src[e]]
// ---------------------------------------------------------------------------
__global__ void aggregate_kernel(const float* __restrict__ x,
                                 const float* __restrict__ eps,
                                 int l, int n)
{
    int warp = (blockIdx.x * blockDim.x + threadIdx.x) >> 5;
    int lane = threadIdx.x & 31;
    if (warp >= n || lane >= VPR) return;
    const float4* h4 = (const float4*)((l == 0) ? x : g_h[l - 1]);

    float s = 1.0f + __ldg(&eps[l]);
    float4 v = h4[warp * VPR + lane];
    float4 acc;
    acc.x = s * v.x; acc.y = s * v.y; acc.z = s * v.z; acc.w = s * v.w;

    int start = g_rowptr[warp];
    int end   = start + g_deg[warp];
    for (int e = start; e < end; e++) {
        int src = __ldg(&g_csrc[e]);
        float4 u = h4[src * VPR + lane];
        acc.x += u.x; acc.y += u.y; acc.z += u.z; acc.w += u.w;
    }
    ((float4*)g_z)[warp * VPR + lane] = acc;
}

// ---------------------------------------------------------------------------
// Per-node 2-layer MLP. w1 transposed in smem -> all weight reads are LDS.128.
// ---------------------------------------------------------------------------
__global__ void mlp_kernel(const float* __restrict__ w1,
                           const float* __restrict__ b1,
                           const float* __restrict__ w2,
                           const float* __restrict__ b2,
                           int l, int n)
{
    __shared__ alignas(16) float sw1t[HID2 * HID];  // [j][k]
    __shared__ alignas(16) float sw2 [HID2 * HID];  // [j][i]
    __shared__ float sb1[HID2];
    __shared__ float sb2[HID];

    const float* w1l = w1 + (size_t)l * HID * HID2;
    const float* w2l = w2 + (size_t)l * HID2 * HID;
    for (int idx = threadIdx.x; idx < HID * HID2; idx += blockDim.x) {
        int k = idx / HID2, j = idx % HID2;
        sw1t[j * HID + k] = w1l[idx];
        sw2[idx] = w2l[idx];
    }
    if (threadIdx.x < HID2) sb1[threadIdx.x] = b1[l * HID2 + threadIdx.x];
    if (threadIdx.x < HID)  sb2[threadIdx.x] = b2[l * HID + threadIdx.x];
    __syncthreads();

    int node = blockIdx.x * blockDim.x + threadIdx.x;
    if (node >= n) return;

    float4 zr[VPR];
    const float4* zp = (const float4*)(g_z + (size_t)node * HID);
#pragma unroll
    for (int c = 0; c < VPR; c++) zr[c] = zp[c];

    float4 acc[VPR];
#pragma unroll
    for (int c = 0; c < VPR; c++) acc[c] = make_float4(0.f, 0.f, 0.f, 0.f);

    const float4* w1p = (const float4*)sw1t;
    const float4* w2p = (const float4*)sw2;

    for (int j = 0; j < HID2; j++) {
        float t0 = 0.f, t1 = 0.f, t2 = 0.f, t3 = 0.f;
#pragma unroll
        for (int c = 0; c < VPR; c++) {
            float4 w = w1p[j * VPR + c];
            t0 = fmaf(zr[c].x, w.x, t0);
            t1 = fmaf(zr[c].y, w.y, t1);
            t2 = fmaf(zr[c].z, w.z, t2);
            t3 = fmaf(zr[c].w, w.w, t3);
        }
        float t = fmaxf((t0 + t1) + (t2 + t3) + sb1[j], 0.0f);
#pragma unroll
        for (int c = 0; c < VPR; c++) {
            float4 w = w2p[j * VPR + c];
            acc[c].x = fmaf(t, w.x, acc[c].x);
            acc[c].y = fmaf(t, w.y, acc[c].y);
            acc[c].z = fmaf(t, w.z, acc[c].z);
            acc[c].w = fmaf(t, w.w, acc[c].w);
        }
    }

    float4* op = (float4*)(g_h[l] + (size_t)node * HID);
#pragma unroll
    for (int c = 0; c < VPR; c++) {
        float4 v;
        v.x = fmaxf(acc[c].x + sb2[4*c+0], 0.0f);
        v.y = fmaxf(acc[c].y + sb2[4*c+1], 0.0f);
        v.z = fmaxf(acc[c].z + sb2[4*c+2], 0.0f);
        v.w = fmaxf(acc[c].w + sb2[4*c+3], 0.0f);
        op[c] = v;
    }
}

// ---------------------------------------------------------------------------
// Final: out = concat(x, h1, h2, h3) @ lin_w + lin_b   (float4 weight reads)
// ---------------------------------------------------------------------------
__global__ void final_kernel(const float* __restrict__ x,
                             const float* __restrict__ lw,
                             const float* __restrict__ lb,
                             float* __restrict__ out, int n)
{
    __shared__ alignas(16) float slw[(NL + 1) * HID * HID];  // [208][52]
    __shared__ float slb[HID];
    for (int i = threadIdx.x; i < (NL + 1) * HID * HID; i += blockDim.x)
        slw[i] = lw[i];
    if (threadIdx.x < HID) slb[threadIdx.x] = lb[threadIdx.x];
    __syncthreads();

    int node = blockIdx.x * blockDim.x + threadIdx.x;
    if (node >= n) return;

    float4 acc[VPR];
#pragma unroll
    for (int c = 0; c < VPR; c++) {
        acc[c].x = slb[4*c+0]; acc[c].y = slb[4*c+1];
        acc[c].z = slb[4*c+2]; acc[c].w = slb[4*c+3];
    }

    const float4* wp4 = (const float4*)slw;
#pragma unroll
    for (int s = 0; s < NL + 1; s++) {
        const float* hp = (s == 0) ? (x + (size_t)node * HID)
                                   : (g_h[s - 1] + (size_t)node * HID);
        for (int k = 0; k < HID; k++) {
            float v = __ldg(&hp[k]);
            int wrow = (s * HID + k) * VPR;
#pragma unroll
            for (int c = 0; c < VPR; c++) {
                float4 w = wp4[wrow + c];
                acc[c].x = fmaf(v, w.x, acc[c].x);
                acc[c].y = fmaf(v, w.y, acc[c].y);
                acc[c].z = fmaf(v, w.z, acc[c].z);
                acc[c].w = fmaf(v, w.w, acc[c].w);
            }
        }
    }

    float4* op = (float4*)(out + (size_t)node * HID);
#pragma unroll
    for (int c = 0; c < VPR; c++) op[c] = acc[c];
}

// ---------------------------------------------------------------------------
extern "C" void kernel_launch(void* const* d_in, const int* in_sizes, int n_in,
                              void* d_out, int out_size)
{
    const float* x    = (const float*)d_in[0];
    const int*   ei   = (const int*)  d_in[1];
    const float* w1   = (const float*)d_in[2];
    const float* b1   = (const float*)d_in[3];
    const float* w2   = (const float*)d_in[4];
    const float* b2   = (const float*)d_in[5];
    const float* eps  = (const float*)d_in[6];
    const float* lw   = (const float*)d_in[7];
    const float* lb   = (const float*)d_in[8];
    float* out = (float*)d_out;

    int n = in_sizes[0] / HID;
    int E = in_sizes[1] / 2;

    int nodeBlocks  = (n + 255) / 256;
    int edgeBlocks  = (E + 255) / 256;
    int aggBlocks   = (n * 32 + 255) / 256;  // warp per node
    int mlpBlocks   = (n + 127) / 128;

    // Build dst-CSR (once per call, reused by all 3 layers)
    zero_deg_kernel<<<nodeBlocks, 256>>>(n);
    count_kernel<<<edgeBlocks, 256>>>(ei, E);
    scan_kernel<<<1, 1024>>>(n);
    place_kernel<<<edgeBlocks, 256>>>(ei, E);

    for (int l = 0; l < NL; l++) {
        aggregate_kernel<<<aggBlocks, 256>>>(x, eps, l, n);
        mlp_kernel<<<mlpBlocks, 128>>>(w1, b1, w2, b2, l, n);
    }
    final_kernel<<<mlpBlocks, 128>>>(x, lw, lb, out, n);
}

// round 3
// speedup vs baseline: 1.2782x; 1.1477x over previous
#include <cuda_runtime.h>
#include <cstdint>

#define N_NODES_MAX 100000
#define E_MAX       3200000
#define HID   52
#define HID2  104
#define NL    3
#define VPR   13   // float4 per 52-float row

#define SCAN_BLK 1024
#define MAX_SCAN_BLOCKS ((N_NODES_MAX + SCAN_BLK - 1) / SCAN_BLK)

// Scratch (allocation-free)
__device__ float g_h[NL][N_NODES_MAX * HID];
__device__ float g_z[N_NODES_MAX * HID];
__device__ int   g_deg[N_NODES_MAX];
__device__ int   g_rowptr[N_NODES_MAX];
__device__ int   g_cur[N_NODES_MAX];
__device__ int   g_csrc[E_MAX];
__device__ int   g_bsum[MAX_SCAN_BLOCKS];
__device__ int   g_boff[MAX_SCAN_BLOCKS];

// ---------------------------------------------------------------------------
// CSR build: zero -> count -> (block scan, sum scan, offset add) -> place
// ---------------------------------------------------------------------------
__global__ void zero_deg_kernel(int n)
{
    int i = blockIdx.x * blockDim.x + threadIdx.x;
    if (i < n) g_deg[i] = 0;
}

__global__ void count_kernel(const int* __restrict__ ei, int E)
{
    int e = blockIdx.x * blockDim.x + threadIdx.x;
    if (e < E) atomicAdd(&g_deg[__ldg(&ei[E + e])], 1);  // no return -> RED
}

// per-block exclusive scan of g_deg -> g_rowptr (block-local), totals -> g_bsum
__global__ void scan1_kernel(int n)
{
    __shared__ int s[2][SCAN_BLK];
    int tid = threadIdx.x;
    int i = blockIdx.x * SCAN_BLK + tid;
    int v = (i < n) ? g_deg[i] : 0;
    int cur = 0;
    s[0][tid] = v;
    __syncthreads();
#pragma unroll
    for (int off = 1; off < SCAN_BLK; off <<= 1) {
        int nv = s[cur][tid] + ((tid >= off) ? s[cur][tid - off] : 0);
        s[1 - cur][tid] = nv;
        cur = 1 - cur;
        __syncthreads();
    }
    if (i < n) g_rowptr[i] = s[cur][tid] - v;   // exclusive, block-local
    if (tid == SCAN_BLK - 1) g_bsum[blockIdx.x] = s[cur][tid];
}

// tiny serial scan of block sums (nb <= 98)
__global__ void scan2_kernel(int nb)
{
    if (threadIdx.x == 0) {
        int acc = 0;
        for (int b = 0; b < nb; b++) { g_boff[b] = acc; acc += g_bsum[b]; }
    }
}

// add block offsets; init cursor
__global__ void scan3_kernel(int n)
{
    int i = blockIdx.x * blockDim.x + threadIdx.x;
    if (i >= n) return;
    int r = g_rowptr[i] + g_boff[i / SCAN_BLK];
    g_rowptr[i] = r;
    g_cur[i] = r;
}

__global__ void place_kernel(const int* __restrict__ ei, int E)
{
    int e = blockIdx.x * blockDim.x + threadIdx.x;
    if (e >= E) return;
    int src = __ldg(&ei[e]);
    int dst = __ldg(&ei[E + e]);
    int pos = atomicAdd(&g_cur[dst], 1);
    g_csrc[pos] = src;
}

// ---------------------------------------------------------------------------
// Aggregate: thread t -> (node = t/13, chunk c = t%13). All 32 lanes live.
// z[node] = (1+eps)*h_in[node] + sum_{src in CSR[node]} h_in[src]
// Edge loop unrolled x4 for memory-level parallelism.
// ---------------------------------------------------------------------------
__global__ void aggregate_kernel(const float* __restrict__ x,
                                 const float* __restrict__ eps,
                                 int l, int n)
{
    int t = blockIdx.x * blockDim.x + threadIdx.x;
    if (t >= n * VPR) return;
    int node = t / VPR;
    int c = t - node * VPR;

    const float4* __restrict__ h4 =
        (const float4*)((l == 0) ? x : g_h[l - 1]);

    float s = 1.0f + __ldg(&eps[l]);
    float4 v = __ldg(&h4[node * VPR + c]);
    float ax = s * v.x, ay = s * v.y, az = s * v.z, aw = s * v.w;

    int e   = g_rowptr[node];
    int end = e + g_deg[node];

    for (; e + 4 <= end; e += 4) {
        int s0 = __ldg(&g_csrc[e]);
        int s1 = __ldg(&g_csrc[e + 1]);
        int s2 = __ldg(&g_csrc[e + 2]);
        int s3 = __ldg(&g_csrc[e + 3]);
        float4 u0 = __ldg(&h4[s0 * VPR + c]);
        float4 u1 = __ldg(&h4[s1 * VPR + c]);
        float4 u2 = __ldg(&h4[s2 * VPR + c]);
        float4 u3 = __ldg(&h4[s3 * VPR + c]);
        ax += (u0.x + u1.x) + (u2.x + u3.x);
        ay += (u0.y + u1.y) + (u2.y + u3.y);
        az += (u0.z + u1.z) + (u2.z + u3.z);
        aw += (u0.w + u1.w) + (u2.w + u3.w);
    }
    for (; e < end; e++) {
        int s0 = __ldg(&g_csrc[e]);
        float4 u0 = __ldg(&h4[s0 * VPR + c]);
        ax += u0.x; ay += u0.y; az += u0.z; aw += u0.w;
    }

    float4 out; out.x = ax; out.y = ay; out.z = az; out.w = aw;
    ((float4*)g_z)[node * VPR + c] = out;
}

// ---------------------------------------------------------------------------
// Per-node 2-layer MLP. Weights as float4 broadcasts from smem; FMA-bound.
// ---------------------------------------------------------------------------
__global__ void mlp_kernel(const float* __restrict__ w1,
                           const float* __restrict__ b1,
                           const float* __restrict__ w2,
                           const float* __restrict__ b2,
                           int l, int n)
{
    __shared__ alignas(16) float sw1t[HID2 * HID];  // [j][k]
    __shared__ alignas(16) float sw2 [HID2 * HID];  // [j][i]
    __shared__ float sb1[HID2];
    __shared__ float sb2[HID];

    const float* w1l = w1 + (size_t)l * HID * HID2;
    const float* w2l = w2 + (size_t)l * HID2 * HID;
    for (int idx = threadIdx.x; idx < HID * HID2; idx += blockDim.x) {
        int k = idx / HID2, j = idx % HID2;
        sw1t[j * HID + k] = w1l[idx];
        sw2[idx] = w2l[idx];
    }
    if (threadIdx.x < HID2) sb1[threadIdx.x] = b1[l * HID2 + threadIdx.x];
    if (threadIdx.x < HID)  sb2[threadIdx.x] = b2[l * HID + threadIdx.x];
    __syncthreads();

    int node = blockIdx.x * blockDim.x + threadIdx.x;
    if (node >= n) return;

    float4 zr[VPR];
    const float4* zp = (const float4*)(g_z + (size_t)node * HID);
#pragma unroll
    for (int c = 0; c < VPR; c++) zr[c] = zp[c];

    float4 acc[VPR];
#pragma unroll
    for (int c = 0; c < VPR; c++) acc[c] = make_float4(0.f, 0.f, 0.f, 0.f);

    const float4* w1p = (const float4*)sw1t;
    const float4* w2p = (const float4*)sw2;

    for (int j = 0; j < HID2; j++) {
        float t0 = 0.f, t1 = 0.f, t2 = 0.f, t3 = 0.f;
#pragma unroll
        for (int c = 0; c < VPR; c++) {
            float4 w = w1p[j * VPR + c];
            t0 = fmaf(zr[c].x, w.x, t0);
            t1 = fmaf(zr[c].y, w.y, t1);
            t2 = fmaf(zr[c].z, w.z, t2);
            t3 = fmaf(zr[c].w, w.w, t3);
        }
        float t = fmaxf((t0 + t1) + (t2 + t3) + sb1[j], 0.0f);
#pragma unroll
        for (int c = 0; c < VPR; c++) {
            float4 w = w2p[j * VPR + c];
            acc[c].x = fmaf(t, w.x, acc[c].x);
            acc[c].y = fmaf(t, w.y, acc[c].y);
            acc[c].z = fmaf(t, w.z, acc[c].z);
            acc[c].w = fmaf(t, w.w, acc[c].w);
        }
    }

    float4* op = (float4*)(g_h[l] + (size_t)node * HID);
#pragma unroll
    for (int c = 0; c < VPR; c++) {
        float4 v;
        v.x = fmaxf(acc[c].x + sb2[4*c+0], 0.0f);
        v.y = fmaxf(acc[c].y + sb2[4*c+1], 0.0f);
        v.z = fmaxf(acc[c].z + sb2[4*c+2], 0.0f);
        v.w = fmaxf(acc[c].w + sb2[4*c+3], 0.0f);
        op[c] = v;
    }
}

// ---------------------------------------------------------------------------
// Final: out = concat(x, h1, h2, h3) @ lin_w + lin_b
// ---------------------------------------------------------------------------
__global__ void final_kernel(const float* __restrict__ x,
                             const float* __restrict__ lw,
                             const float* __restrict__ lb,
                             float* __restrict__ out, int n)
{
    __shared__ alignas(16) float slw[(NL + 1) * HID * HID];
    __shared__ float slb[HID];
    for (int i = threadIdx.x; i < (NL + 1) * HID * HID; i += blockDim.x)
        slw[i] = lw[i];
    if (threadIdx.x < HID) slb[threadIdx.x] = lb[threadIdx.x];
    __syncthreads();

    int node = blockIdx.x * blockDim.x + threadIdx.x;
    if (node >= n) return;

    float4 acc[VPR];
#pragma unroll
    for (int c = 0; c < VPR; c++) {
        acc[c].x = slb[4*c+0]; acc[c].y = slb[4*c+1];
        acc[c].z = slb[4*c+2]; acc[c].w = slb[4*c+3];
    }

    const float4* wp4 = (const float4*)slw;
#pragma unroll
    for (int s = 0; s < NL + 1; s++) {
        const float* hp = (s == 0) ? (x + (size_t)node * HID)
                                   : (g_h[s - 1] + (size_t)node * HID);
        for (int k = 0; k < HID; k++) {
            float v = __ldg(&hp[k]);
            int wrow = (s * HID + k) * VPR;
#pragma unroll
            for (int c = 0; c < VPR; c++) {
                float4 w = wp4[wrow + c];
                acc[c].x = fmaf(v, w.x, acc[c].x);
                acc[c].y = fmaf(v, w.y, acc[c].y);
                acc[c].z = fmaf(v, w.z, acc[c].z);
                acc[c].w = fmaf(v, w.w, acc[c].w);
            }
        }
    }

    float4* op = (float4*)(out + (size_t)node * HID);
#pragma unroll
    for (int c = 0; c < VPR; c++) op[c] = acc[c];
}

// ---------------------------------------------------------------------------
extern "C" void kernel_launch(void* const* d_in, const int* in_sizes, int n_in,
                              void* d_out, int out_size)
{
    const float* x    = (const float*)d_in[0];
    const int*   ei   = (const int*)  d_in[1];
    const float* w1   = (const float*)d_in[2];
    const float* b1   = (const float*)d_in[3];
    const float* w2   = (const float*)d_in[4];
    const float* b2   = (const float*)d_in[5];
    const float* eps  = (const float*)d_in[6];
    const float* lw   = (const float*)d_in[7];
    const float* lb   = (const float*)d_in[8];
    float* out = (float*)d_out;

    int n = in_sizes[0] / HID;
    int E = in_sizes[1] / 2;

    int nodeBlocks = (n + 255) / 256;
    int edgeBlocks = (E + 255) / 256;
    int aggBlocks  = (n * VPR + 255) / 256;
    int mlpBlocks  = (n + 127) / 128;
    int scanBlocks = (n + SCAN_BLK - 1) / SCAN_BLK;

    // Build dst-CSR (reused by all 3 layers)
    zero_deg_kernel<<<nodeBlocks, 256>>>(n);
    count_kernel<<<edgeBlocks, 256>>>(ei, E);
    scan1_kernel<<<scanBlocks, SCAN_BLK>>>(n);
    scan2_kernel<<<1, 32>>>(scanBlocks);
    scan3_kernel<<<nodeBlocks, 256>>>(n);
    place_kernel<<<edgeBlocks, 256>>>(ei, E);

    for (int l = 0; l < NL; l++) {
        aggregate_kernel<<<aggBlocks, 256>>>(x, eps, l, n);
        mlp_kernel<<<mlpBlocks, 128>>>(w1, b1, w2, b2, l, n);
    }
    final_kernel<<<mlpBlocks, 128>>>(x, lw, lb, out, n);
}

// round 4
// speedup vs baseline: 1.2803x; 1.0017x over previous
#include <cuda_runtime.h>
#include <cstdint>

#define N_NODES_MAX 100000
#define E_MAX       3200000
#define HID   52
#define HID2  104
#define NL    3
#define VPR   13   // float4 per 52-float row

#define SCAN_BLK 1024
#define MAX_SCAN_BLOCKS ((N_NODES_MAX + SCAN_BLK - 1) / SCAN_BLK)
#define CSR_CAP (E_MAX + 4 * N_NODES_MAX)

// Scratch (allocation-free, zero-initialized at load).
// Row N_NODES_MAX (index n) is a sentinel row that is NEVER written -> stays 0.
__device__ float g_hin[(N_NODES_MAX + 1) * HID];          // padded copy of x
__device__ float g_h[NL][(N_NODES_MAX + 1) * HID];        // layer outputs
__device__ float g_z[N_NODES_MAX * HID];
__device__ int   g_deg[N_NODES_MAX];
__device__ int   g_rowptr[N_NODES_MAX];
__device__ int   g_cur[N_NODES_MAX];
__device__ alignas(16) int g_csrc[CSR_CAP];
__device__ int   g_bsum[MAX_SCAN_BLOCKS];
__device__ int   g_boff[MAX_SCAN_BLOCKS];

// ---------------------------------------------------------------------------
// Copy x into padded scratch; zero the sentinel row n.
// ---------------------------------------------------------------------------
__global__ void copy_x_kernel(const float* __restrict__ x, int n)
{
    int i = blockIdx.x * blockDim.x + threadIdx.x;
    int total = n * VPR;
    if (i < total) {
        ((float4*)g_hin)[i] = ((const float4*)x)[i];
    } else if (i < total + VPR) {
        ((float4*)g_hin)[i] = make_float4(0.f, 0.f, 0.f, 0.f);
    }
}

// ---------------------------------------------------------------------------
// CSR build: zero -> count -> padded scan -> fill pads -> place
// ---------------------------------------------------------------------------
__global__ void zero_deg_kernel(int n)
{
    int i = blockIdx.x * blockDim.x + threadIdx.x;
    if (i < n) g_deg[i] = 0;
}

__global__ void count_kernel(const int* __restrict__ ei, int E)
{
    int e = blockIdx.x * blockDim.x + threadIdx.x;
    if (e < E) atomicAdd(&g_deg[__ldg(&ei[E + e])], 1);  // no return -> RED
}

// per-block exclusive scan of PADDED degrees -> g_rowptr; block totals -> g_bsum
__global__ void scan1_kernel(int n)
{
    __shared__ int s[2][SCAN_BLK];
    int tid = threadIdx.x;
    int i = blockIdx.x * SCAN_BLK + tid;
    int v = (i < n) ? ((g_deg[i] + 3) & ~3) : 0;
    int cur = 0;
    s[0][tid] = v;
    __syncthreads();
#pragma unroll
    for (int off = 1; off < SCAN_BLK; off <<= 1) {
        int nv = s[cur][tid] + ((tid >= off) ? s[cur][tid - off] : 0);
        s[1 - cur][tid] = nv;
        cur = 1 - cur;
        __syncthreads();
    }
    if (i < n) g_rowptr[i] = s[cur][tid] - v;   // exclusive, block-local
    if (tid == SCAN_BLK - 1) g_bsum[blockIdx.x] = s[cur][tid];
}

__global__ void scan2_kernel(int nb)
{
    if (threadIdx.x == 0) {
        int acc = 0;
        for (int b = 0; b < nb; b++) { g_boff[b] = acc; acc += g_bsum[b]; }
    }
}

__global__ void scan3_kernel(int n)
{
    int i = blockIdx.x * blockDim.x + threadIdx.x;
    if (i >= n) return;
    int r = g_rowptr[i] + g_boff[i / SCAN_BLK];
    g_rowptr[i] = r;
    g_cur[i] = r;
}

// fill padding slots [rowptr+deg, rowptr+degPadded) with sentinel row index n
__global__ void fillpad_kernel(int n)
{
    int i = blockIdx.x * blockDim.x + threadIdx.x;
    if (i >= n) return;
    int d  = g_deg[i];
    int dp = (d + 3) & ~3;
    int base = g_rowptr[i];
    for (int k = d; k < dp; k++) g_csrc[base + k] = n;
}

__global__ void place_kernel(const int* __restrict__ ei, int E)
{
    int e = blockIdx.x * blockDim.x + threadIdx.x;
    if (e >= E) return;
    int src = __ldg(&ei[e]);
    int dst = __ldg(&ei[E + e]);
    int pos = atomicAdd(&g_cur[dst], 1);
    g_csrc[pos] = src;
}

// ---------------------------------------------------------------------------
// Aggregate: thread t -> (node = t/13, chunk c = t%13). All segments are
// 4-edge padded and 16B-aligned: indices load as int4, no remainder.
// z[node] = (1+eps)*h_in[node] + sum_{src in CSR[node]} h_in[src]
// ---------------------------------------------------------------------------
__global__ void aggregate_kernel(const float* __restrict__ eps, int l, int n)
{
    int t = blockIdx.x * blockDim.x + threadIdx.x;
    if (t >= n * VPR) return;
    int node = t / VPR;
    int c = t - node * VPR;

    const float4* __restrict__ h4 =
        (const float4*)((l == 0) ? g_hin : g_h[l - 1]);

    float s = 1.0f + __ldg(&eps[l]);
    float4 v = __ldg(&h4[node * VPR + c]);
    float ax = s * v.x, ay = s * v.y, az = s * v.z, aw = s * v.w;

    int rp    = g_rowptr[node];
    int iters = (g_deg[node] + 3) >> 2;
    const int4* cs4 = (const int4*)g_csrc;
    int base = rp >> 2;

    for (int it = 0; it < iters; it++) {
        int4 sidx = __ldg(&cs4[base + it]);
        float4 u0 = __ldg(&h4[sidx.x * VPR + c]);
        float4 u1 = __ldg(&h4[sidx.y * VPR + c]);
        float4 u2 = __ldg(&h4[sidx.z * VPR + c]);
        float4 u3 = __ldg(&h4[sidx.w * VPR + c]);
        ax += (u0.x + u1.x) + (u2.x + u3.x);
        ay += (u0.y + u1.y) + (u2.y + u3.y);
        az += (u0.z + u1.z) + (u2.z + u3.z);
        aw += (u0.w + u1.w) + (u2.w + u3.w);
    }

    float4 out; out.x = ax; out.y = ay; out.z = az; out.w = aw;
    ((float4*)g_z)[node * VPR + c] = out;
}

// ---------------------------------------------------------------------------
// Per-node 2-layer MLP (FMA-bound; weights broadcast from smem as float4).
// ---------------------------------------------------------------------------
__global__ void mlp_kernel(const float* __restrict__ w1,
                           const float* __restrict__ b1,
                           const float* __restrict__ w2,
                           const float* __restrict__ b2,
                           int l, int n)
{
    __shared__ alignas(16) float sw1t[HID2 * HID];  // [j][k]
    __shared__ alignas(16) float sw2 [HID2 * HID];  // [j][i]
    __shared__ float sb1[HID2];
    __shared__ float sb2[HID];

    const float* w1l = w1 + (size_t)l * HID * HID2;
    const float* w2l = w2 + (size_t)l * HID2 * HID;
    for (int idx = threadIdx.x; idx < HID * HID2; idx += blockDim.x) {
        int k = idx / HID2, j = idx % HID2;
        sw1t[j * HID + k] = w1l[idx];
        sw2[idx] = w2l[idx];
    }
    if (threadIdx.x < HID2) sb1[threadIdx.x] = b1[l * HID2 + threadIdx.x];
    if (threadIdx.x < HID)  sb2[threadIdx.x] = b2[l * HID + threadIdx.x];
    __syncthreads();

    int node = blockIdx.x * blockDim.x + threadIdx.x;
    if (node >= n) return;

    float4 zr[VPR];
    const float4* zp = (const float4*)(g_z + (size_t)node * HID);
#pragma unroll
    for (int c = 0; c < VPR; c++) zr[c] = zp[c];

    float4 acc[VPR];
#pragma unroll
    for (int c = 0; c < VPR; c++) acc[c] = make_float4(0.f, 0.f, 0.f, 0.f);

    const float4* w1p = (const float4*)sw1t;
    const float4* w2p = (const float4*)sw2;

    for (int j = 0; j < HID2; j++) {
        float t0 = 0.f, t1 = 0.f, t2 = 0.f, t3 = 0.f;
#pragma unroll
        for (int c = 0; c < VPR; c++) {
            float4 w = w1p[j * VPR + c];
            t0 = fmaf(zr[c].x, w.x, t0);
            t1 = fmaf(zr[c].y, w.y, t1);
            t2 = fmaf(zr[c].z, w.z, t2);
            t3 = fmaf(zr[c].w, w.w, t3);
        }
        float t = fmaxf((t0 + t1) + (t2 + t3) + sb1[j], 0.0f);
#pragma unroll
        for (int c = 0; c < VPR; c++) {
            float4 w = w2p[j * VPR + c];
            acc[c].x = fmaf(t, w.x, acc[c].x);
            acc[c].y = fmaf(t, w.y, acc[c].y);
            acc[c].z = fmaf(t, w.z, acc[c].z);
            acc[c].w = fmaf(t, w.w, acc[c].w);
        }
    }

    float4* op = (float4*)(g_h[l] + (size_t)node * HID);
#pragma unroll
    for (int c = 0; c < VPR; c++) {
        float4 v;
        v.x = fmaxf(acc[c].x + sb2[4*c+0], 0.0f);
        v.y = fmaxf(acc[c].y + sb2[4*c+1], 0.0f);
        v.z = fmaxf(acc[c].z + sb2[4*c+2], 0.0f);
        v.w = fmaxf(acc[c].w + sb2[4*c+3], 0.0f);
        op[c] = v;
    }
}

// ---------------------------------------------------------------------------
// Final: out = concat(x, h1, h2, h3) @ lin_w + lin_b
// ---------------------------------------------------------------------------
__global__ void final_kernel(const float* __restrict__ lw,
                             const float* __restrict__ lb,
                             float* __restrict__ out, int n)
{
    __shared__ alignas(16) float slw[(NL + 1) * HID * HID];
    __shared__ float slb[HID];
    for (int i = threadIdx.x; i < (NL + 1) * HID * HID; i += blockDim.x)
        slw[i] = lw[i];
    if (threadIdx.x < HID) slb[threadIdx.x] = lb[threadIdx.x];
    __syncthreads();

    int node = blockIdx.x * blockDim.x + threadIdx.x;
    if (node >= n) return;

    float4 acc[VPR];
#pragma unroll
    for (int c = 0; c < VPR; c++) {
        acc[c].x = slb[4*c+0]; acc[c].y = slb[4*c+1];
        acc[c].z = slb[4*c+2]; acc[c].w = slb[4*c+3];
    }

    const float4* wp4 = (const float4*)slw;
#pragma unroll
    for (int s = 0; s < NL + 1; s++) {
        const float* hp = (s == 0) ? (g_hin + (size_t)node * HID)
                                   : (g_h[s - 1] + (size_t)node * HID);
        for (int k = 0; k < HID; k++) {
            float v = __ldg(&hp[k]);
            int wrow = (s * HID + k) * VPR;
#pragma unroll
            for (int c = 0; c < VPR; c++) {
                float4 w = wp4[wrow + c];
                acc[c].x = fmaf(v, w.x, acc[c].x);
                acc[c].y = fmaf(v, w.y, acc[c].y);
                acc[c].z = fmaf(v, w.z, acc[c].z);
                acc[c].w = fmaf(v, w.w, acc[c].w);
            }
        }
    }

    float4* op = (float4*)(out + (size_t)node * HID);
#pragma unroll
    for (int c = 0; c < VPR; c++) op[c] = acc[c];
}

// ---------------------------------------------------------------------------
extern "C" void kernel_launch(void* const* d_in, const int* in_sizes, int n_in,
                              void* d_out, int out_size)
{
    const float* x    = (const float*)d_in[0];
    const int*   ei   = (const int*)  d_in[1];
    const float* w1   = (const float*)d_in[2];
    const float* b1   = (const float*)d_in[3];
    const float* w2   = (const float*)d_in[4];
    const float* b2   = (const float*)d_in[5];
    const float* eps  = (const float*)d_in[6];
    const float* lw   = (const float*)d_in[7];
    const float* lb   = (const float*)d_in[8];
    float* out = (float*)d_out;

    int n = in_sizes[0] / HID;
    int E = in_sizes[1] / 2;

    int nodeBlocks = (n + 255) / 256;
    int edgeBlocks = (E + 255) / 256;
    int copyBlocks = ((n + 1) * VPR + 255) / 256;
    int aggBlocks  = (n * VPR + 255) / 256;
    int mlpBlocks  = (n + 127) / 128;
    int scanBlocks = (n + SCAN_BLK - 1) / SCAN_BLK;

    // Padded copy of x (sentinel row n = 0)
    copy_x_kernel<<<copyBlocks, 256>>>(x, n);

    // Build dst-CSR with 4-padded segments (reused by all 3 layers)
    zero_deg_kernel<<<nodeBlocks, 256>>>(n);
    count_kernel<<<edgeBlocks, 256>>>(ei, E);
    scan1_kernel<<<scanBlocks, SCAN_BLK>>>(n);
    scan2_kernel<<<1, 32>>>(scanBlocks);
    scan3_kernel<<<nodeBlocks, 256>>>(n);
    fillpad_kernel<<<nodeBlocks, 256>>>(n);
    place_kernel<<<edgeBlocks, 256>>>(ei, E);

    for (int l = 0; l < NL; l++) {
        aggregate_kernel<<<aggBlocks, 256>>>(eps, l, n);
        mlp_kernel<<<mlpBlocks, 128>>>(w1, b1, w2, b2, l, n);
    }
    final_kernel<<<mlpBlocks, 128>>>(lw, lb, out, n);
}

// round 5
// speedup vs baseline: 1.8313x; 1.4304x over previous
#include <cuda_runtime.h>
#include <cuda_fp16.h>
#include <cstdint>

#define N_NODES_MAX 100000
#define E_MAX       3200000
#define HID   52
#define HID2  104
#define NL    3
#define VPR   13   // float4 per 52-float row
#define HPR   13   // uint2 (4 halves) per 52-half row

#define SCAN_BLK 1024
#define MAX_SCAN_BLOCKS ((N_NODES_MAX + SCAN_BLK - 1) / SCAN_BLK)
#define CSR_CAP (E_MAX + 4 * N_NODES_MAX)

// Scratch (allocation-free, zero-initialized at load).
// Row index n is a sentinel row that is NEVER written -> stays 0 forever.
__device__ __half g_hin[(N_NODES_MAX + 1) * HID];       // padded fp16 copy of x
__device__ __half g_h[NL][(N_NODES_MAX + 1) * HID];     // fp16 layer outputs
__device__ float  g_z[N_NODES_MAX * HID];
__device__ int    g_deg[N_NODES_MAX];
__device__ int    g_rowptr[N_NODES_MAX];
__device__ int    g_cur[N_NODES_MAX];
__device__ alignas(16) int g_csrc[CSR_CAP];
__device__ int    g_bsum[MAX_SCAN_BLOCKS];
__device__ int    g_boff[MAX_SCAN_BLOCKS];

__device__ __forceinline__ uint32_t pack_half2(float a, float b)
{
    __half2 h = __floats2half2_rn(a, b);
    return *(uint32_t*)&h;
}

// ---------------------------------------------------------------------------
// Fused: zero degrees + convert x -> fp16 padded copy (incl. sentinel row)
// ---------------------------------------------------------------------------
__global__ void prep_kernel(const float* __restrict__ x, int n)
{
    int i = blockIdx.x * blockDim.x + threadIdx.x;
    if (i < n) g_deg[i] = 0;
    int total = n * VPR;
    if (i < total) {
        float4 v = __ldg(&((const float4*)x)[i]);
        uint2 u;
        u.x = pack_half2(v.x, v.y);
        u.y = pack_half2(v.z, v.w);
        ((uint2*)g_hin)[i] = u;
    } else if (i < total + VPR) {
        ((uint2*)g_hin)[i] = make_uint2(0u, 0u);
    }
}

// ---------------------------------------------------------------------------
// count: 4 edges per thread (int4 reads of dst half of edge_index)
// ---------------------------------------------------------------------------
__global__ void count_kernel(const int* __restrict__ ei, int E)
{
    int t = blockIdx.x * blockDim.x + threadIdx.x;
    int E4 = E >> 2;
    if (t < E4) {
        int4 d = __ldg(&((const int4*)(ei + E))[t]);
        atomicAdd(&g_deg[d.x], 1);
        atomicAdd(&g_deg[d.y], 1);
        atomicAdd(&g_deg[d.z], 1);
        atomicAdd(&g_deg[d.w], 1);
    } else {
        int e = (E4 << 2) + (t - E4);
        if (e < E) atomicAdd(&g_deg[__ldg(&ei[E + e])], 1);
    }
}

// per-block exclusive scan of PADDED degrees; block totals -> g_bsum
__global__ void scan1_kernel(int n)
{
    __shared__ int s[2][SCAN_BLK];
    int tid = threadIdx.x;
    int i = blockIdx.x * SCAN_BLK + tid;
    int v = (i < n) ? ((g_deg[i] + 3) & ~3) : 0;
    int cur = 0;
    s[0][tid] = v;
    __syncthreads();
#pragma unroll
    for (int off = 1; off < SCAN_BLK; off <<= 1) {
        int nv = s[cur][tid] + ((tid >= off) ? s[cur][tid - off] : 0);
        s[1 - cur][tid] = nv;
        cur = 1 - cur;
        __syncthreads();
    }
    if (i < n) g_rowptr[i] = s[cur][tid] - v;   // exclusive, block-local
    if (tid == SCAN_BLK - 1) g_bsum[blockIdx.x] = s[cur][tid];
}

// scan of <=128 block sums, one block (Hillis-Steele in smem)
__global__ void scan2_kernel(int nb)
{
    __shared__ int s[2][128];
    int tid = threadIdx.x;
    int v = (tid < nb) ? g_bsum[tid] : 0;
    int cur = 0;
    s[0][tid] = v;
    __syncthreads();
#pragma unroll
    for (int off = 1; off < 128; off <<= 1) {
        int nv = s[cur][tid] + ((tid >= off) ? s[cur][tid - off] : 0);
        s[1 - cur][tid] = nv;
        cur = 1 - cur;
        __syncthreads();
    }
    if (tid < nb) g_boff[tid] = s[cur][tid] - v;
}

// fused: add block offsets, init cursor, fill sentinel pads
__global__ void scan3_fill_kernel(int n)
{
    int i = blockIdx.x * blockDim.x + threadIdx.x;
    if (i >= n) return;
    int r = g_rowptr[i] + g_boff[i / SCAN_BLK];
    g_rowptr[i] = r;
    g_cur[i] = r;
    int d  = g_deg[i];
    int dp = (d + 3) & ~3;
    for (int k = d; k < dp; k++) g_csrc[r + k] = n;
}

// place: 4 edges per thread (int4 reads of src and dst halves)
__global__ void place_kernel(const int* __restrict__ ei, int E)
{
    int t = blockIdx.x * blockDim.x + threadIdx.x;
    int E4 = E >> 2;
    if (t < E4) {
        int4 s = __ldg(&((const int4*)ei)[t]);
        int4 d = __ldg(&((const int4*)(ei + E))[t]);
        g_csrc[atomicAdd(&g_cur[d.x], 1)] = s.x;
        g_csrc[atomicAdd(&g_cur[d.y], 1)] = s.y;
        g_csrc[atomicAdd(&g_cur[d.z], 1)] = s.z;
        g_csrc[atomicAdd(&g_cur[d.w], 1)] = s.w;
    } else {
        int e = (E4 << 2) + (t - E4);
        if (e < E) {
            int src = __ldg(&ei[e]);
            int dst = __ldg(&ei[E + e]);
            g_csrc[atomicAdd(&g_cur[dst], 1)] = src;
        }
    }
}

// ---------------------------------------------------------------------------
// Aggregate (fp16 gather, fp32 accumulate): thread t -> (node=t/13, c=t%13).
// Each thread owns 4 halves (8B) of the 104B row. Segments padded to 4 edges.
// ---------------------------------------------------------------------------
__global__ void aggregate_kernel(const float* __restrict__ eps, int l, int n)
{
    int t = blockIdx.x * blockDim.x + threadIdx.x;
    if (t >= n * HPR) return;
    int node = t / HPR;
    int c = t - node * HPR;

    const uint2* __restrict__ h8 =
        (const uint2*)((l == 0) ? g_hin : g_h[l - 1]);

    float s = 1.0f + __ldg(&eps[l]);
    uint2 u = __ldg(&h8[node * HPR + c]);
    float2 f0 = __half22float2(*(__half2*)&u.x);
    float2 f1 = __half22float2(*(__half2*)&u.y);
    float ax = s * f0.x, ay = s * f0.y, az = s * f1.x, aw = s * f1.y;

    int rp    = g_rowptr[node];
    int iters = (g_deg[node] + 3) >> 2;
    const int4* cs4 = (const int4*)g_csrc;
    int base = rp >> 2;

    for (int it = 0; it < iters; it++) {
        int4 sidx = __ldg(&cs4[base + it]);
        uint2 u0 = __ldg(&h8[sidx.x * HPR + c]);
        uint2 u1 = __ldg(&h8[sidx.y * HPR + c]);
        uint2 u2 = __ldg(&h8[sidx.z * HPR + c]);
        uint2 u3 = __ldg(&h8[sidx.w * HPR + c]);
        float2 a0 = __half22float2(*(__half2*)&u0.x);
        float2 b0 = __half22float2(*(__half2*)&u0.y);
        float2 a1 = __half22float2(*(__half2*)&u1.x);
        float2 b1 = __half22float2(*(__half2*)&u1.y);
        float2 a2 = __half22float2(*(__half2*)&u2.x);
        float2 b2 = __half22float2(*(__half2*)&u2.y);
        float2 a3 = __half22float2(*(__half2*)&u3.x);
        float2 b3 = __half22float2(*(__half2*)&u3.y);
        ax += (a0.x + a1.x) + (a2.x + a3.x);
        ay += (a0.y + a1.y) + (a2.y + a3.y);
        az += (b0.x + b1.x) + (b2.x + b3.x);
        aw += (b0.y + b1.y) + (b2.y + b3.y);
    }

    float4 out; out.x = ax; out.y = ay; out.z = az; out.w = aw;
    ((float4*)g_z)[node * VPR + c] = out;
}

// ---------------------------------------------------------------------------
// Per-node 2-layer MLP (FMA-bound). Reads z fp32, writes h fp16.
// ---------------------------------------------------------------------------
__global__ void mlp_kernel(const float* __restrict__ w1,
                           const float* __restrict__ b1,
                           const float* __restrict__ w2,
                           const float* __restrict__ b2,
                           int l, int n)
{
    __shared__ alignas(16) float sw1t[HID2 * HID];  // [j][k]
    __shared__ alignas(16) float sw2 [HID2 * HID];  // [j][i]
    __shared__ float sb1[HID2];
    __shared__ float sb2[HID];

    const float* w1l = w1 + (size_t)l * HID * HID2;
    const float* w2l = w2 + (size_t)l * HID2 * HID;
    for (int idx = threadIdx.x; idx < HID * HID2; idx += blockDim.x) {
        int k = idx / HID2, j = idx % HID2;
        sw1t[j * HID + k] = w1l[idx];
        sw2[idx] = w2l[idx];
    }
    if (threadIdx.x < HID2) sb1[threadIdx.x] = b1[l * HID2 + threadIdx.x];
    if (threadIdx.x < HID)  sb2[threadIdx.x] = b2[l * HID + threadIdx.x];
    __syncthreads();

    int node = blockIdx.x * blockDim.x + threadIdx.x;
    if (node >= n) return;

    float4 zr[VPR];
    const float4* zp = (const float4*)(g_z + (size_t)node * HID);
#pragma unroll
    for (int c = 0; c < VPR; c++) zr[c] = zp[c];

    float4 acc[VPR];
#pragma unroll
    for (int c = 0; c < VPR; c++) acc[c] = make_float4(0.f, 0.f, 0.f, 0.f);

    const float4* w1p = (const float4*)sw1t;
    const float4* w2p = (const float4*)sw2;

    for (int j = 0; j < HID2; j++) {
        float t0 = 0.f, t1 = 0.f, t2 = 0.f, t3 = 0.f;
#pragma unroll
        for (int c = 0; c < VPR; c++) {
            float4 w = w1p[j * VPR + c];
            t0 = fmaf(zr[c].x, w.x, t0);
            t1 = fmaf(zr[c].y, w.y, t1);
            t2 = fmaf(zr[c].z, w.z, t2);
            t3 = fmaf(zr[c].w, w.w, t3);
        }
        float t = fmaxf((t0 + t1) + (t2 + t3) + sb1[j], 0.0f);
#pragma unroll
        for (int c = 0; c < VPR; c++) {
            float4 w = w2p[j * VPR + c];
            acc[c].x = fmaf(t, w.x, acc[c].x);
            acc[c].y = fmaf(t, w.y, acc[c].y);
            acc[c].z = fmaf(t, w.z, acc[c].z);
            acc[c].w = fmaf(t, w.w, acc[c].w);
        }
    }

    uint2* op = (uint2*)(g_h[l] + (size_t)node * HID);
#pragma unroll
    for (int c = 0; c < VPR; c++) {
        float vx = fmaxf(acc[c].x + sb2[4*c+0], 0.0f);
        float vy = fmaxf(acc[c].y + sb2[4*c+1], 0.0f);
        float vz = fmaxf(acc[c].z + sb2[4*c+2], 0.0f);
        float vw = fmaxf(acc[c].w + sb2[4*c+3], 0.0f);
        uint2 u;
        u.x = pack_half2(vx, vy);
        u.y = pack_half2(vz, vw);
        op[c] = u;
    }
}

// ---------------------------------------------------------------------------
// Final: out = concat(x, h1, h2, h3) @ lin_w + lin_b  (h in fp16, out fp32)
// ---------------------------------------------------------------------------
__global__ void final_kernel(const float* __restrict__ lw,
                             const float* __restrict__ lb,
                             float* __restrict__ out, int n)
{
    __shared__ alignas(16) float slw[(NL + 1) * HID * HID];
    __shared__ float slb[HID];
    for (int i = threadIdx.x; i < (NL + 1) * HID * HID; i += blockDim.x)
        slw[i] = lw[i];
    if (threadIdx.x < HID) slb[threadIdx.x] = lb[threadIdx.x];
    __syncthreads();

    int node = blockIdx.x * blockDim.x + threadIdx.x;
    if (node >= n) return;

    float4 acc[VPR];
#pragma unroll
    for (int c = 0; c < VPR; c++) {
        acc[c].x = slb[4*c+0]; acc[c].y = slb[4*c+1];
        acc[c].z = slb[4*c+2]; acc[c].w = slb[4*c+3];
    }

    const float4* wp4 = (const float4*)slw;
#pragma unroll
    for (int s = 0; s < NL + 1; s++) {
        const __half* hb = (s == 0) ? g_hin : g_h[s - 1];
        const __half2* hp = (const __half2*)(hb + (size_t)node * HID);
        for (int k2 = 0; k2 < HID / 2; k2++) {
            __half2 hv = __ldg(&hp[k2]);
            float2 f = __half22float2(hv);
            int wrow0 = (s * HID + 2 * k2) * VPR;
            int wrow1 = wrow0 + VPR;
#pragma unroll
            for (int c = 0; c < VPR; c++) {
                float4 w0 = wp4[wrow0 + c];
                acc[c].x = fmaf(f.x, w0.x, acc[c].x);
                acc[c].y = fmaf(f.x, w0.y, acc[c].y);
                acc[c].z = fmaf(f.x, w0.z, acc[c].z);
                acc[c].w = fmaf(f.x, w0.w, acc[c].w);
            }
#pragma unroll
            for (int c = 0; c < VPR; c++) {
                float4 w1 = wp4[wrow1 + c];
                acc[c].x = fmaf(f.y, w1.x, acc[c].x);
                acc[c].y = fmaf(f.y, w1.y, acc[c].y);
                acc[c].z = fmaf(f.y, w1.z, acc[c].z);
                acc[c].w = fmaf(f.y, w1.w, acc[c].w);
            }
        }
    }

    float4* op = (float4*)(out + (size_t)node * HID);
#pragma unroll
    for (int c = 0; c < VPR; c++) op[c] = acc[c];
}

// ---------------------------------------------------------------------------
extern "C" void kernel_launch(void* const* d_in, const int* in_sizes, int n_in,
                              void* d_out, int out_size)
{
    const float* x    = (const float*)d_in[0];
    const int*   ei   = (const int*)  d_in[1];
    const float* w1   = (const float*)d_in[2];
    const float* b1   = (const float*)d_in[3];
    const float* w2   = (const float*)d_in[4];
    const float* b2   = (const float*)d_in[5];
    const float* eps  = (const float*)d_in[6];
    const float* lw   = (const float*)d_in[7];
    const float* lb   = (const float*)d_in[8];
    float* out = (float*)d_out;

    int n = in_sizes[0] / HID;
    int E = in_sizes[1] / 2;

    int nodeBlocks = (n + 255) / 256;
    int prepBlocks = (n * VPR + 13 + 255) / 256;
    int cntBlocks  = ((E >> 2) + (E & 3) + 255) / 256;
    int aggBlocks  = (n * HPR + 255) / 256;
    int mlpBlocks  = (n + 127) / 128;
    int scanBlocks = (n + SCAN_BLK - 1) / SCAN_BLK;

    prep_kernel<<<prepBlocks, 256>>>(x, n);
    count_kernel<<<cntBlocks, 256>>>(ei, E);
    scan1_kernel<<<scanBlocks, SCAN_BLK>>>(n);
    scan2_kernel<<<1, 128>>>(scanBlocks);
    scan3_fill_kernel<<<nodeBlocks, 256>>>(n);
    place_kernel<<<cntBlocks, 256>>>(ei, E);

    for (int l = 0; l < NL; l++) {
        aggregate_kernel<<<aggBlocks, 256>>>(eps, l, n);
        mlp_kernel<<<mlpBlocks, 128>>>(w1, b1, w2, b2, l, n);
    }
    final_kernel<<<mlpBlocks, 128>>>(lw, lb, out, n);
}

// round 6
// speedup vs baseline: 1.9278x; 1.0527x over previous
#include <cuda_runtime.h>
#include <cuda_fp16.h>
#include <cstdint>

#define N_NODES_MAX 100000
#define E_MAX       3200000
#define HID   52
#define HID2  104
#define NL    3
#define VPR   13   // float4 per 52-float row
#define HPR   13   // uint2 (4 halves) per 52-half row
#define QPR   13   // ulonglong2 per 52-float row

#define SCAN_BLK 1024
#define MAX_SCAN_BLOCKS ((N_NODES_MAX + SCAN_BLK - 1) / SCAN_BLK)
#define CSR_CAP (E_MAX + 8 * N_NODES_MAX)

typedef unsigned long long u64;

// Scratch (allocation-free, zero-initialized). Row n = sentinel, never written.
__device__ __half g_hin[(N_NODES_MAX + 1) * HID];
__device__ __half g_h[NL][(N_NODES_MAX + 1) * HID];
__device__ float  g_z[N_NODES_MAX * HID];
__device__ int    g_deg[N_NODES_MAX];
__device__ int    g_rowptr[N_NODES_MAX];
__device__ int    g_cur[N_NODES_MAX];
__device__ alignas(16) int g_csrc[CSR_CAP];
__device__ int    g_bsum[MAX_SCAN_BLOCKS];
__device__ int    g_boff[MAX_SCAN_BLOCKS];

__device__ __forceinline__ uint32_t pack_half2(float a, float b)
{
    __half2 h = __floats2half2_rn(a, b);
    return *(uint32_t*)&h;
}
__device__ __forceinline__ u64 fma2(u64 a, u64 b, u64 c)
{
    u64 d;
    asm("fma.rn.f32x2 %0, %1, %2, %3;" : "=l"(d) : "l"(a), "l"(b), "l"(c));
    return d;
}
__device__ __forceinline__ u64 pack2(float x, float y)
{
    u64 r; asm("mov.b64 %0, {%1, %2};" : "=l"(r) : "f"(x), "f"(y)); return r;
}
__device__ __forceinline__ void unpack2(u64 v, float& x, float& y)
{
    asm("mov.b64 {%0, %1}, %2;" : "=f"(x), "=f"(y) : "l"(v));
}

// ---------------------------------------------------------------------------
__global__ void prep_kernel(const float* __restrict__ x, int n)
{
    int i = blockIdx.x * blockDim.x + threadIdx.x;
    if (i < n) g_deg[i] = 0;
    int total = n * VPR;
    if (i < total) {
        float4 v = __ldg(&((const float4*)x)[i]);
        uint2 u;
        u.x = pack_half2(v.x, v.y);
        u.y = pack_half2(v.z, v.w);
        ((uint2*)g_hin)[i] = u;
    } else if (i < total + VPR) {
        ((uint2*)g_hin)[i] = make_uint2(0u, 0u);
    }
}

__global__ void count_kernel(const int* __restrict__ ei, int E)
{
    int t = blockIdx.x * blockDim.x + threadIdx.x;
    int E4 = E >> 2;
    if (t < E4) {
        int4 d = __ldg(&((const int4*)(ei + E))[t]);
        atomicAdd(&g_deg[d.x], 1);
        atomicAdd(&g_deg[d.y], 1);
        atomicAdd(&g_deg[d.z], 1);
        atomicAdd(&g_deg[d.w], 1);
    } else {
        int e = (E4 << 2) + (t - E4);
        if (e < E) atomicAdd(&g_deg[__ldg(&ei[E + e])], 1);
    }
}

// exclusive scan of degrees padded to 8
__global__ void scan1_kernel(int n)
{
    __shared__ int s[2][SCAN_BLK];
    int tid = threadIdx.x;
    int i = blockIdx.x * SCAN_BLK + tid;
    int v = (i < n) ? ((g_deg[i] + 7) & ~7) : 0;
    int cur = 0;
    s[0][tid] = v;
    __syncthreads();
#pragma unroll
    for (int off = 1; off < SCAN_BLK; off <<= 1) {
        int nv = s[cur][tid] + ((tid >= off) ? s[cur][tid - off] : 0);
        s[1 - cur][tid] = nv;
        cur = 1 - cur;
        __syncthreads();
    }
    if (i < n) g_rowptr[i] = s[cur][tid] - v;
    if (tid == SCAN_BLK - 1) g_bsum[blockIdx.x] = s[cur][tid];
}

__global__ void scan2_kernel(int nb)
{
    __shared__ int s[2][128];
    int tid = threadIdx.x;
    int v = (tid < nb) ? g_bsum[tid] : 0;
    int cur = 0;
    s[0][tid] = v;
    __syncthreads();
#pragma unroll
    for (int off = 1; off < 128; off <<= 1) {
        int nv = s[cur][tid] + ((tid >= off) ? s[cur][tid - off] : 0);
        s[1 - cur][tid] = nv;
        cur = 1 - cur;
        __syncthreads();
    }
    if (tid < nb) g_boff[tid] = s[cur][tid] - v;
}

__global__ void scan3_fill_kernel(int n)
{
    int i = blockIdx.x * blockDim.x + threadIdx.x;
    if (i >= n) return;
    int r = g_rowptr[i] + g_boff[i / SCAN_BLK];
    g_rowptr[i] = r;
    g_cur[i] = r;
    int d  = g_deg[i];
    int dp = (d + 7) & ~7;
    for (int k = d; k < dp; k++) g_csrc[r + k] = n;
}

__global__ void place_kernel(const int* __restrict__ ei, int E)
{
    int t = blockIdx.x * blockDim.x + threadIdx.x;
    int E4 = E >> 2;
    if (t < E4) {
        int4 s = __ldg(&((const int4*)ei)[t]);
        int4 d = __ldg(&((const int4*)(ei + E))[t]);
        g_csrc[atomicAdd(&g_cur[d.x], 1)] = s.x;
        g_csrc[atomicAdd(&g_cur[d.y], 1)] = s.y;
        g_csrc[atomicAdd(&g_cur[d.z], 1)] = s.z;
        g_csrc[atomicAdd(&g_cur[d.w], 1)] = s.w;
    } else {
        int e = (E4 << 2) + (t - E4);
        if (e < E) {
            int src = __ldg(&ei[e]);
            int dst = __ldg(&ei[E + e]);
            g_csrc[atomicAdd(&g_cur[dst], 1)] = src;
        }
    }
}

// ---------------------------------------------------------------------------
// Aggregate (fp16 gather, fp32 accumulate), 8 edges in flight per iteration.
// ---------------------------------------------------------------------------
__global__ void aggregate_kernel(const float* __restrict__ eps, int l, int n)
{
    int t = blockIdx.x * blockDim.x + threadIdx.x;
    if (t >= n * HPR) return;
    int node = t / HPR;
    int c = t - node * HPR;

    const uint2* __restrict__ h8 =
        (const uint2*)((l == 0) ? g_hin : g_h[l - 1]);

    float s = 1.0f + __ldg(&eps[l]);
    uint2 u = __ldg(&h8[node * HPR + c]);
    float2 f0 = __half22float2(*(__half2*)&u.x);
    float2 f1 = __half22float2(*(__half2*)&u.y);
    float ax = s * f0.x, ay = s * f0.y, az = s * f1.x, aw = s * f1.y;

    int rp    = g_rowptr[node];
    int iters = (g_deg[node] + 7) >> 3;
    const int4* cs4 = (const int4*)g_csrc;
    int base = rp >> 2;

    for (int it = 0; it < iters; it++) {
        int4 i0 = __ldg(&cs4[base + 2 * it]);
        int4 i1 = __ldg(&cs4[base + 2 * it + 1]);
        uint2 u0 = __ldg(&h8[i0.x * HPR + c]);
        uint2 u1 = __ldg(&h8[i0.y * HPR + c]);
        uint2 u2 = __ldg(&h8[i0.z * HPR + c]);
        uint2 u3 = __ldg(&h8[i0.w * HPR + c]);
        uint2 u4 = __ldg(&h8[i1.x * HPR + c]);
        uint2 u5 = __ldg(&h8[i1.y * HPR + c]);
        uint2 u6 = __ldg(&h8[i1.z * HPR + c]);
        uint2 u7 = __ldg(&h8[i1.w * HPR + c]);
#define ACC8(uu) { \
        float2 pa = __half22float2(*(__half2*)&uu.x); \
        float2 pb = __half22float2(*(__half2*)&uu.y); \
        ax += pa.x; ay += pa.y; az += pb.x; aw += pb.y; }
        ACC8(u0); ACC8(u1); ACC8(u2); ACC8(u3);
        ACC8(u4); ACC8(u5); ACC8(u6); ACC8(u7);
#undef ACC8
    }

    float4 out; out.x = ax; out.y = ay; out.z = az; out.w = aw;
    ((float4*)g_z)[node * VPR + c] = out;
}

// ---------------------------------------------------------------------------
// Per-node 2-layer MLP with packed fp32x2 FMA (FFMA2).
// ---------------------------------------------------------------------------
__global__ void __launch_bounds__(128) mlp_kernel(
        const float* __restrict__ w1, const float* __restrict__ b1,
        const float* __restrict__ w2, const float* __restrict__ b2,
        int l, int n)
{
    __shared__ alignas(16) float sw1t[HID2 * HID];  // [j][k]
    __shared__ alignas(16) float sw2 [HID2 * HID];  // [j][i]
    __shared__ float sb1[HID2];
    __shared__ float sb2[HID];

    const float* w1l = w1 + (size_t)l * HID * HID2;
    const float* w2l = w2 + (size_t)l * HID2 * HID;
    for (int idx = threadIdx.x; idx < HID * HID2; idx += blockDim.x) {
        int k = idx / HID2, j = idx % HID2;
        sw1t[j * HID + k] = w1l[idx];
        sw2[idx] = w2l[idx];
    }
    if (threadIdx.x < HID2) sb1[threadIdx.x] = b1[l * HID2 + threadIdx.x];
    if (threadIdx.x < HID)  sb2[threadIdx.x] = b2[l * HID + threadIdx.x];
    __syncthreads();

    int node = blockIdx.x * blockDim.x + threadIdx.x;
    if (node >= n) return;

    u64 zr2[2 * QPR];                 // 26 packed pairs = 52 floats
    const ulonglong2* zp = (const ulonglong2*)(g_z + (size_t)node * HID);
#pragma unroll
    for (int c = 0; c < QPR; c++) {
        ulonglong2 q = zp[c];
        zr2[2*c] = q.x; zr2[2*c+1] = q.y;
    }

    u64 acc2[2 * QPR];
#pragma unroll
    for (int c = 0; c < 2 * QPR; c++) acc2[c] = 0ull;

    const ulonglong2* w1q = (const ulonglong2*)sw1t;
    const ulonglong2* w2q = (const ulonglong2*)sw2;

    for (int j = 0; j < HID2; j++) {
        u64 t2 = 0ull;
#pragma unroll
        for (int c = 0; c < QPR; c++) {
            ulonglong2 w = w1q[j * QPR + c];
            t2 = fma2(zr2[2*c],   w.x, t2);
            t2 = fma2(zr2[2*c+1], w.y, t2);
        }
        float t0, t1; unpack2(t2, t0, t1);
        float t = fmaxf(t0 + t1 + sb1[j], 0.0f);
        u64 tt = pack2(t, t);
#pragma unroll
        for (int c = 0; c < QPR; c++) {
            ulonglong2 w = w2q[j * QPR + c];
            acc2[2*c]   = fma2(tt, w.x, acc2[2*c]);
            acc2[2*c+1] = fma2(tt, w.y, acc2[2*c+1]);
        }
    }

    uint2* op = (uint2*)(g_h[l] + (size_t)node * HID);
#pragma unroll
    for (int c = 0; c < QPR; c++) {
        float a0, a1, a2, a3;
        unpack2(acc2[2*c],   a0, a1);
        unpack2(acc2[2*c+1], a2, a3);
        float vx = fmaxf(a0 + sb2[4*c+0], 0.0f);
        float vy = fmaxf(a1 + sb2[4*c+1], 0.0f);
        float vz = fmaxf(a2 + sb2[4*c+2], 0.0f);
        float vw = fmaxf(a3 + sb2[4*c+3], 0.0f);
        uint2 u;
        u.x = pack_half2(vx, vy);
        u.y = pack_half2(vz, vw);
        op[c] = u;
    }
}

// ---------------------------------------------------------------------------
// Final linear with packed fp32x2 FMA.
// ---------------------------------------------------------------------------
__global__ void __launch_bounds__(128) final_kernel(
        const float* __restrict__ lw, const float* __restrict__ lb,
        float* __restrict__ out, int n)
{
    __shared__ alignas(16) float slw[(NL + 1) * HID * HID];
    __shared__ float slb[HID];
    for (int i = threadIdx.x; i < (NL + 1) * HID * HID; i += blockDim.x)
        slw[i] = lw[i];
    if (threadIdx.x < HID) slb[threadIdx.x] = lb[threadIdx.x];
    __syncthreads();

    int node = blockIdx.x * blockDim.x + threadIdx.x;
    if (node >= n) return;

    u64 acc2[2 * QPR];
#pragma unroll
    for (int c = 0; c < QPR; c++) {
        acc2[2*c]   = pack2(slb[4*c+0], slb[4*c+1]);
        acc2[2*c+1] = pack2(slb[4*c+2], slb[4*c+3]);
    }

    const ulonglong2* wq = (const ulonglong2*)slw;
#pragma unroll
    for (int s = 0; s < NL + 1; s++) {
        const __half* hb = (s == 0) ? g_hin : g_h[s - 1];
        const __half2* hp = (const __half2*)(hb + (size_t)node * HID);
        for (int k2 = 0; k2 < HID / 2; k2++) {
            __half2 hv = __ldg(&hp[k2]);
            float2 f = __half22float2(hv);
            u64 v0 = pack2(f.x, f.x);
            u64 v1 = pack2(f.y, f.y);
            int r0 = (s * HID + 2 * k2) * QPR;
            int r1 = r0 + QPR;
#pragma unroll
            for (int c = 0; c < QPR; c++) {
                ulonglong2 w = wq[r0 + c];
                acc2[2*c]   = fma2(v0, w.x, acc2[2*c]);
                acc2[2*c+1] = fma2(v0, w.y, acc2[2*c+1]);
            }
#pragma unroll
            for (int c = 0; c < QPR; c++) {
                ulonglong2 w = wq[r1 + c];
                acc2[2*c]   = fma2(v1, w.x, acc2[2*c]);
                acc2[2*c+1] = fma2(v1, w.y, acc2[2*c+1]);
            }
        }
    }

    ulonglong2* op = (ulonglong2*)(out + (size_t)node * HID);
#pragma unroll
    for (int c = 0; c < QPR; c++) {
        ulonglong2 q; q.x = acc2[2*c]; q.y = acc2[2*c+1];
        op[c] = q;
    }
}

// ---------------------------------------------------------------------------
extern "C" void kernel_launch(void* const* d_in, const int* in_sizes, int n_in,
                              void* d_out, int out_size)
{
    const float* x    = (const float*)d_in[0];
    const int*   ei   = (const int*)  d_in[1];
    const float* w1   = (const float*)d_in[2];
    const float* b1   = (const float*)d_in[3];
    const float* w2   = (const float*)d_in[4];
    const float* b2   = (const float*)d_in[5];
    const float* eps  = (const float*)d_in[6];
    const float* lw   = (const float*)d_in[7];
    const float* lb   = (const float*)d_in[8];
    float* out = (float*)d_out;

    int n = in_sizes[0] / HID;
    int E = in_sizes[1] / 2;

    int nodeBlocks = (n + 255) / 256;
    int prepBlocks = (n * VPR + 13 + 255) / 256;
    int cntBlocks  = ((E >> 2) + (E & 3) + 255) / 256;
    int aggBlocks  = (n * HPR + 255) / 256;
    int mlpBlocks  = (n + 127) / 128;
    int scanBlocks = (n + SCAN_BLK - 1) / SCAN_BLK;

    prep_kernel<<<prepBlocks, 256>>>(x, n);
    count_kernel<<<cntBlocks, 256>>>(ei, E);
    scan1_kernel<<<scanBlocks, SCAN_BLK>>>(n);
    scan2_kernel<<<1, 128>>>(scanBlocks);
    scan3_fill_kernel<<<nodeBlocks, 256>>>(n);
    place_kernel<<<cntBlocks, 256>>>(ei, E);

    for (int l = 0; l < NL; l++) {
        aggregate_kernel<<<aggBlocks, 256>>>(eps, l, n);
        mlp_kernel<<<mlpBlocks, 128>>>(w1, b1, w2, b2, l, n);
    }
    final_kernel<<<mlpBlocks, 128>>>(lw, lb, out, n);
}